// round 13
// baseline (speedup 1.0000x reference)
#include <cuda_runtime.h>

// ---------------------------------------------------------------------------
// WaveConv3d: 2-level db4 3D DWT (periodic, pad 8) -> per-voxel channel mix on
// the 8 coarsest bands -> inverse DWT (level-1 details zero -> lo-only).
// R13: level-2 forward reordered x-first with register-streamed x-DWT fused
// into the yz kernel (f2x_yz) — removes dwt_s<37,529> and its 100MB
// intermediate (stage DRAM 381->181MB). Inverse side keeps R12's i2x_zy.
// ---------------------------------------------------------------------------

#define NV 12167            // 23^3

#define FLO {-0.010597401784997278f,  0.032883011666982945f,  0.030841381835986965f, \
             -0.18703481171888114f,  -0.02798376941698385f,   0.6308807679295904f,  \
              0.7148465705525415f,    0.23037781330885523f}
#define FHI { 0.23037781330885523f,  -0.7148465705525415f,    0.6308807679295904f,  \
              0.02798376941698385f,  -0.18703481171888114f,  -0.030841381835986965f,\
              0.032883011666982945f,  0.010597401784997278f}

// Scratch (max live = 8 bands * 320*23^3 = 31.1M floats)
__device__ float g_buf1[31147520];
__device__ float g_buf2[31147520];

// ---------------------------------------------------------------------------
// Forward DWT along a strided axis (level-1 x-pass). Sliding window, 1 row/thread.
// ---------------------------------------------------------------------------
template<int N, int INNER, bool HI>
__global__ void dwt_s(const float* __restrict__ in, float* __restrict__ olo,
                      float* __restrict__ ohi, unsigned total) {
    constexpr int K = (N + 8) / 2 + 1;
    const float LO[8] = FLO;
    const float HIc[8] = FHI;
    unsigned g = blockIdx.x * blockDim.x + threadIdx.x;
    if (g >= total) return;
    unsigned ii = g % INNER;
    unsigned o  = g / INNER;
    const float* bp = in  + (size_t)o * (N * INNER) + ii;
    float*       lp = olo + (size_t)o * (K * INNER) + ii;
    float*       hp = HI ? ohi + (size_t)o * (K * INNER) + ii : nullptr;

    float w[8];
#pragma unroll
    for (int t = 0; t < 8; t++) w[t] = bp[(N - 8 + t) * INNER];

#pragma unroll
    for (int j = 0; j < K; j++) {
        float alo = 0.f, ahi = 0.f;
#pragma unroll
        for (int t = 0; t < 8; t++) {
            alo = fmaf(w[t], LO[7 - t], alo);
            if (HI) ahi = fmaf(w[t], HIc[7 - t], ahi);
        }
        lp[j * INNER] = alo;
        if (HI) hp[j * INNER] = ahi;
        if (j < K - 1) {
            int q0 = (2 * j) % N;
            int q1 = (2 * j + 1) % N;
#pragma unroll
            for (int t = 0; t < 6; t++) w[t] = w[t + 2];
            w[6] = bp[q0 * INNER];
            w[7] = bp[q1 * INNER];
        }
    }
}

// ---------------------------------------------------------------------------
// Level-1 forward, fused y+z, lo-only, paired outputs (R5 version).
// ---------------------------------------------------------------------------
__global__ void f1_yz(const float* __restrict__ in, float* __restrict__ out) {
    __shared__ float s0[64 * 64];
    __shared__ float s1[37 * 65];
    const float LO[8] = FLO;
    unsigned tid = threadIdx.x;
    size_t blk = blockIdx.x;
    const float* gp = in + blk * 4096;
#pragma unroll 4
    for (int t = tid; t < 4096; t += 256) s0[t] = gp[t];
    __syncthreads();
    for (int u = tid; u < 19 * 64; u += 256) {       // y-DWT pairs
        int z = u & 63, jp = u >> 6;
        float w[10];
#pragma unroll
        for (int t = 0; t < 10; t++) {
            int q = (4 * jp - 8 + t) & 63;
            w[t] = s0[q * 64 + z];
        }
        float a0 = 0.f, a1 = 0.f;
#pragma unroll
        for (int s = 0; s < 8; s++) {
            a0 = fmaf(LO[s], w[7 - s], a0);
            a1 = fmaf(LO[s], w[9 - s], a1);
        }
        s1[(2 * jp) * 65 + z] = a0;
        if (2 * jp + 1 < 37) s1[(2 * jp + 1) * 65 + z] = a1;
    }
    __syncthreads();
    float* op = out + blk * 1369;
    for (int u = tid; u < 37 * 19; u += 256) {       // z-DWT pairs
        int ph = u % 19, y = u / 19;
        float w[10];
#pragma unroll
        for (int t = 0; t < 10; t++) {
            int q = (4 * ph - 8 + t) & 63;
            w[t] = s1[y * 65 + q];
        }
        float a0 = 0.f, a1 = 0.f;
#pragma unroll
        for (int s = 0; s < 8; s++) {
            a0 = fmaf(LO[s], w[7 - s], a0);
            a1 = fmaf(LO[s], w[9 - s], a1);
        }
        op[y * 37 + 2 * ph] = a0;
        if (2 * ph + 1 < 37) op[y * 37 + 2 * ph + 1] = a1;
    }
}

// ---------------------------------------------------------------------------
// Level-2 forward, FUSED x+y+z. Block = (bc, j2), j2 in [0,23).
// x-DWT (lo+hi) register-streamed from the (320,37,37,37) tensor (8 wrap-
// indexed slices, coalesced over the 1369-element slice; source is
// L2-resident), then paired y/z-DWT on both volumes -> 8 bands directly.
// Bands: dx=0 (lo) -> slots 0..3, dx=1 (hi) -> slots 4..7 (slot=4dx+2dy+dz).
// smem 24.6KB.
// ---------------------------------------------------------------------------
__global__ void f2x_yz(const float* __restrict__ in, float* __restrict__ out,
                       long long SBl) {
    __shared__ float s0l[1369], s0h[1369];
    __shared__ float sly[2][23 * 37];   // y-DWT lo part, per volume
    __shared__ float shy[2][23 * 37];   // y-DWT hi part, per volume
    const float LO[8] = FLO;
    const float HIc[8] = FHI;
    unsigned tid = threadIdx.x;
    unsigned bc = blockIdx.x / 23;
    int j2 = (int)(blockIdx.x % 23);

    // --- x-DWT, register-streamed (block-uniform tap offsets) ---
    const float* bp = in + (size_t)bc * (37 * 1369);
    int q[8];
#pragma unroll
    for (int t = 0; t < 8; t++) {
        int qq = 2 * j2 - 8 + t;
        if (qq < 0) qq += 37; else if (qq >= 37) qq -= 37;
        q[t] = qq;
    }
    for (int t = tid; t < 1369; t += 256) {
        float al = 0.f, ah = 0.f;
#pragma unroll
        for (int tt = 0; tt < 8; tt++) {
            float v = bp[(size_t)q[tt] * 1369 + t];
            al = fmaf(v, LO[7 - tt], al);
            ah = fmaf(v, HIc[7 - tt], ah);
        }
        s0l[t] = al;
        s0h[t] = ah;
    }
    __syncthreads();

    // --- y-DWT lo+hi, paired, both volumes ---
    for (int u = tid; u < 2 * 12 * 37; u += 256) {
        int v  = u / (12 * 37);
        int v2 = u % (12 * 37);
        int z = v2 % 37, jp = v2 / 37;
        const float* s0 = v ? s0h : s0l;
        float w[10];
#pragma unroll
        for (int t = 0; t < 10; t++) {
            int qq = 4 * jp - 8 + t;
            if (qq < 0) qq += 37; else if (qq >= 37) qq -= 37;
            w[t] = s0[qq * 37 + z];
        }
        float l0 = 0.f, h0 = 0.f, l1 = 0.f, h1 = 0.f;
#pragma unroll
        for (int s = 0; s < 8; s++) {
            l0 = fmaf(LO[s],  w[7 - s], l0);
            h0 = fmaf(HIc[s], w[7 - s], h0);
            l1 = fmaf(LO[s],  w[9 - s], l1);
            h1 = fmaf(HIc[s], w[9 - s], h1);
        }
        sly[v][(2 * jp) * 37 + z] = l0;
        shy[v][(2 * jp) * 37 + z] = h0;
        if (2 * jp + 1 < 23) {
            sly[v][(2 * jp + 1) * 37 + z] = l1;
            shy[v][(2 * jp + 1) * 37 + z] = h1;
        }
    }
    __syncthreads();

    // --- z-DWT, paired, both volumes -> 8 band outputs ---
    size_t obase = ((size_t)bc * 23 + j2) * 529;
    for (int u = tid; u < 2 * 23 * 12; u += 256) {
        int v  = u / (23 * 12);
        int v2 = u % (23 * 12);
        int ph = v2 % 12, y = v2 / 12;
        const float* sl = sly[v];
        const float* sh = shy[v];
        float wl[10], wh[10];
#pragma unroll
        for (int t = 0; t < 10; t++) {
            int qq = 4 * ph - 8 + t;
            if (qq < 0) qq += 37; else if (qq >= 37) qq -= 37;
            wl[t] = sl[y * 37 + qq];
            wh[t] = sh[y * 37 + qq];
        }
        float ll0 = 0.f, lh0 = 0.f, hl0 = 0.f, hh0 = 0.f;
        float ll1 = 0.f, lh1 = 0.f, hl1 = 0.f, hh1 = 0.f;
#pragma unroll
        for (int s = 0; s < 8; s++) {
            ll0 = fmaf(LO[s],  wl[7 - s], ll0);  lh0 = fmaf(HIc[s], wl[7 - s], lh0);
            hl0 = fmaf(LO[s],  wh[7 - s], hl0);  hh0 = fmaf(HIc[s], wh[7 - s], hh0);
            ll1 = fmaf(LO[s],  wl[9 - s], ll1);  lh1 = fmaf(HIc[s], wl[9 - s], lh1);
            hl1 = fmaf(LO[s],  wh[9 - s], hl1);  hh1 = fmaf(HIc[s], wh[9 - s], hh1);
        }
        float* ob = out + (size_t)(4 * v) * SBl + obase + y * 23 + 2 * ph;
        ob[0]           = ll0;   // slot 4v+0 (dy=0,dz=0)
        ob[SBl]         = lh0;   // slot 4v+1 (dy=0,dz=1)
        ob[2 * SBl]     = hl0;   // slot 4v+2 (dy=1,dz=0)
        ob[3 * SBl]     = hh0;   // slot 4v+3
        if (2 * ph + 1 < 23) {
            ob[1]           = ll1;
            ob[SBl + 1]     = lh1;
            ob[2 * SBl + 1] = hl1;
            ob[3 * SBl + 1] = hh1;
        }
    }
}

// ---------------------------------------------------------------------------
// Level-2 inverse, FUSED x+z+y, register-streamed x-IDWT (R12, proven).
// ---------------------------------------------------------------------------
__global__ void i2x_zy(const float* __restrict__ in, float* __restrict__ out,
                       long long SBl) {
    __shared__ float sie[4 * 529];
    __shared__ float sio[4 * 529];
    __shared__ float sle[23 * 37], she[23 * 37];
    __shared__ float slo[23 * 37], sho[23 * 37];
    const float LO[8] = FLO;
    const float HIc[8] = FHI;
    unsigned tid = threadIdx.x;
    unsigned bc = blockIdx.x / 10;
    unsigned xb = blockIdx.x % 10;

    for (int c = 0; c < 2; c++) {
        int xo0 = 4 * (int)xb + 2 * c;
        if (xo0 > 36) break;
        int js = 2 * (int)xb + 1 + c;

        for (int u = tid; u < 4 * 529; u += 256) {
            int m = u / 529, r = u % 529;
            const float* lp = in + (size_t)m * SBl
                              + (size_t)bc * 12167 + (size_t)js * 529 + r;
            const float* hp = lp + 4 * SBl;
            float ae = 0.f, ao = 0.f;
#pragma unroll
            for (int d = 0; d < 4; d++) {
                float vl = lp[d * 529];
                float vh = hp[d * 529];
                ae = fmaf(vl, LO[2 * d + 1], ae);  ae = fmaf(vh, HIc[2 * d + 1], ae);
                ao = fmaf(vl, LO[2 * d],     ao);  ao = fmaf(vh, HIc[2 * d],     ao);
            }
            sie[u] = ae;
            sio[u] = ao;
        }
        __syncthreads();

        for (int u = tid; u < 2 * 23 * 19; u += 256) {
            int p  = u / 437;
            int v2 = u % 437;
            int m  = v2 % 19, y = v2 / 19;
            const float* si = p ? sio : sie;
            float* sl = p ? slo : sle;
            float* sh = p ? sho : she;
            int jz = m + 1;
            float a0 = 0.f, a1 = 0.f, b0 = 0.f, b1 = 0.f;
#pragma unroll
            for (int d = 0; d < 4; d++) {
                int qq = y * 23 + jz + d;
                float v0 = si[qq],           v1 = si[529 + qq];
                float v2f = si[2 * 529 + qq], v3 = si[3 * 529 + qq];
                a0 = fmaf(v0, LO[2 * d + 1], a0);  a0 = fmaf(v1, HIc[2 * d + 1], a0);
                a1 = fmaf(v0, LO[2 * d],     a1);  a1 = fmaf(v1, HIc[2 * d],     a1);
                b0 = fmaf(v2f, LO[2 * d + 1], b0); b0 = fmaf(v3, HIc[2 * d + 1], b0);
                b1 = fmaf(v2f, LO[2 * d],     b1); b1 = fmaf(v3, HIc[2 * d],     b1);
            }
            sl[y * 37 + 2 * m] = a0;  sh[y * 37 + 2 * m] = b0;
            if (2 * m + 1 < 37) {
                sl[y * 37 + 2 * m + 1] = a1;  sh[y * 37 + 2 * m + 1] = b1;
            }
        }
        __syncthreads();

        for (int u = tid; u < 2 * 19 * 37; u += 256) {
            int p  = u / 703;
            int xo = xo0 + p;
            if (xo > 36) continue;
            int v2 = u % 703;
            int z  = v2 % 37, m = v2 / 37;
            const float* sl = p ? slo : sle;
            const float* sh = p ? sho : she;
            int jy = m + 1;
            float a0 = 0.f, a1 = 0.f;
#pragma unroll
            for (int d = 0; d < 4; d++) {
                float vl = sl[(jy + d) * 37 + z];
                float vh = sh[(jy + d) * 37 + z];
                a0 = fmaf(vl, LO[2 * d + 1], a0);  a0 = fmaf(vh, HIc[2 * d + 1], a0);
                a1 = fmaf(vl, LO[2 * d],     a1);  a1 = fmaf(vh, HIc[2 * d],     a1);
            }
            float* op = out + ((size_t)bc * 37 + xo) * 1369;
            op[(2 * m) * 37 + z] = a0;
            if (2 * m + 1 < 37) op[(2 * m + 1) * 37 + z] = a1;
        }
        __syncthreads();
    }
}

// ---------------------------------------------------------------------------
// Level-1 inverse, FUSED x+z+y, lo-only (R9 version, proven).
// ---------------------------------------------------------------------------
__global__ void i1x_yz(const float* __restrict__ in, float* __restrict__ out) {
    __shared__ float ss[5 * 1369];
    __shared__ float s0[1369];
    __shared__ float s1[37 * 65];
    const float LO[8] = FLO;
    unsigned tid = threadIdx.x;
    unsigned bc = blockIdx.x >> 4;
    unsigned xb = blockIdx.x & 15;
    int j0 = 2 * (int)xb + 1;

    const float* gp = in + ((size_t)bc * 37 + j0) * 1369;
#pragma unroll 2
    for (int t = tid; t < 5 * 1369; t += 256) ss[t] = gp[t];
    __syncthreads();

#pragma unroll
    for (int c = 0; c < 4; c++) {
        int xo  = 4 * (int)xb + c;
        int par = c & 1;
        int off = (c >> 1) * 1369;

        for (int t = tid; t < 1369; t += 256) {
            float a = 0.f;
#pragma unroll
            for (int d = 0; d < 4; d++) {
                float fl = par ? LO[2 * d] : LO[2 * d + 1];
                a = fmaf(ss[off + d * 1369 + t], fl, a);
            }
            s0[t] = a;
        }
        __syncthreads();

        for (int u = tid; u < 37 * 32; u += 256) {
            int m = u & 31, y = u >> 5;
            int js = m + 1;
            float a0 = 0.f, a1 = 0.f;
#pragma unroll
            for (int d = 0; d < 4; d++) {
                float v = s0[y * 37 + js + d];
                a0 = fmaf(v, LO[2 * d + 1], a0);
                a1 = fmaf(v, LO[2 * d],     a1);
            }
            s1[y * 65 + 2 * m]     = a0;
            s1[y * 65 + 2 * m + 1] = a1;
        }
        __syncthreads();

        float* op = out + ((size_t)bc * 64 + xo) * 4096;
        for (int u = tid; u < 32 * 64; u += 256) {
            int z = u & 63, m = u >> 6;
            int js = m + 1;
            float a0 = 0.f, a1 = 0.f;
#pragma unroll
            for (int d = 0; d < 4; d++) {
                float v = s1[(js + d) * 65 + z];
                a0 = fmaf(v, LO[2 * d + 1], a0);
                a1 = fmaf(v, LO[2 * d],     a1);
            }
            op[(2 * m) * 64 + z]     = a0;
            op[(2 * m + 1) * 64 + z] = a1;
        }
        __syncthreads();
    }
}

// ---------------------------------------------------------------------------
// Channel mix, ALL 8 bands in one launch (blockIdx.y = band).
// ---------------------------------------------------------------------------
__global__ void chanmix_all(const float* __restrict__ in,
                            float* __restrict__ out, long long SBl,
                            const float* __restrict__ w0, const float* __restrict__ w1,
                            const float* __restrict__ w2, const float* __restrict__ w3,
                            const float* __restrict__ w4, const float* __restrict__ w5,
                            const float* __restrict__ w6, const float* __restrict__ w7) {
    __shared__ float s_in[320][32];
    int k = blockIdx.y;
    const float* w;
    switch (k) {
        case 0: w = w0; break; case 1: w = w1; break;
        case 2: w = w2; break; case 3: w = w3; break;
        case 4: w = w4; break; case 5: w = w5; break;
        case 6: w = w6; break; default: w = w7; break;
    }
    const float* bin  = in  + (long long)k * SBl;
    float*       bout = out + (long long)k * SBl;

    int lane = threadIdx.x;
    int ty   = threadIdx.y;
    int v    = blockIdx.x * 32 + lane;
    bool valid = v < NV;
    int vc = valid ? v : (NV - 1);

    for (int r = ty; r < 320; r += 8)
        s_in[r][lane] = bin[(long long)r * NV + vc];
    __syncthreads();

    float acc[5][8];
#pragma unroll
    for (int a = 0; a < 5; a++)
#pragma unroll
        for (int b = 0; b < 8; b++) acc[a][b] = 0.f;

#pragma unroll 2
    for (int i = 0; i < 40; i += 2) {
        float xv0[8], xv1[8];
#pragma unroll
        for (int b = 0; b < 8; b++) {
            xv0[b] = s_in[b * 40 + i][lane];
            xv1[b] = s_in[b * 40 + i + 1][lane];
        }
        float wv0[5], wv1[5];
#pragma unroll
        for (int oo = 0; oo < 5; oo++) {
            int o = ty + oo * 8;
            wv0[oo] = w[((long long)i * 40 + o) * NV + vc];
            wv1[oo] = w[((long long)(i + 1) * 40 + o) * NV + vc];
        }
#pragma unroll
        for (int oo = 0; oo < 5; oo++)
#pragma unroll
            for (int b = 0; b < 8; b++) {
                acc[oo][b] = fmaf(xv0[b], wv0[oo], acc[oo][b]);
                acc[oo][b] = fmaf(xv1[b], wv1[oo], acc[oo][b]);
            }
    }
    if (!valid) return;
#pragma unroll
    for (int oo = 0; oo < 5; oo++) {
        int o = ty + oo * 8;
#pragma unroll
        for (int b = 0; b < 8; b++)
            bout[((long long)b * 40 + o) * NV + v] = acc[oo][b];
    }
}

// ---------------------------------------------------------------------------
extern "C" void kernel_launch(void* const* d_in, const int* in_sizes, int n_in,
                              void* d_out, int out_size) {
    const float* x = (const float*)d_in[0];
    float* out = (float*)d_out;

    float *b1, *b2;
    cudaGetSymbolAddress((void**)&b1, g_buf1);
    cudaGetSymbolAddress((void**)&b2, g_buf2);

    const long long SBl = 3893440LL;   // 320*23*23*23 (per final band volume)

    auto g = [](unsigned t) { return (t + 255u) / 256u; };

    // --- Level-1 forward: fused yz (lo), then x (lo) ------------------------
    f1_yz<<<320 * 64, 256>>>(x, b1);                        // -> (320,64,37,37)
    { unsigned T = 320u * 1369u;                            // -> (320,37,37,37)
      dwt_s<64, 1369, false><<<g(T), 256>>>(b1, b2, nullptr, T); }

    // --- Level-2 forward: FUSED x (streamed) + yz -> 8 bands -----------------
    f2x_yz<<<320 * 23, 256>>>(b2, b1, SBl);                 // -> 8x(320,23,23,23)

    // --- Channel mix: all 8 bands in one launch (slot == weight index k) ----
    chanmix_all<<<dim3((NV + 31) / 32, 8), dim3(32, 8)>>>(
        b1, b2, SBl,
        (const float*)d_in[1], (const float*)d_in[2],
        (const float*)d_in[3], (const float*)d_in[4],
        (const float*)d_in[5], (const float*)d_in[6],
        (const float*)d_in[7], (const float*)d_in[8]);

    // --- Level-2 inverse: FUSED x+zy, register-streamed x-IDWT --------------
    i2x_zy<<<320 * 10, 256>>>(b2, b1, SBl);                 // -> (320,37,37,37)

    // --- Level-1 inverse: FUSED x+zy (lo) ------------------------------------
    i1x_yz<<<320 * 16, 256>>>(b1, out);                     // -> (320,64,64,64)
}

// round 14
// speedup vs baseline: 1.0294x; 1.0294x over previous
#include <cuda_runtime.h>

// ---------------------------------------------------------------------------
// WaveConv3d: 2-level db4 3D DWT (periodic, pad 8) -> per-voxel channel mix on
// the 8 coarsest bands -> inverse DWT (level-1 details zero -> lo-only).
// R14: chanmix re-tiled (32x20 block, acc[2][8] per thread) to lift occupancy
// from the regfile-bound 37.5% to 62.5%. Pipeline otherwise = R13.
// ---------------------------------------------------------------------------

#define NV 12167            // 23^3

#define FLO {-0.010597401784997278f,  0.032883011666982945f,  0.030841381835986965f, \
             -0.18703481171888114f,  -0.02798376941698385f,   0.6308807679295904f,  \
              0.7148465705525415f,    0.23037781330885523f}
#define FHI { 0.23037781330885523f,  -0.7148465705525415f,    0.6308807679295904f,  \
              0.02798376941698385f,  -0.18703481171888114f,  -0.030841381835986965f,\
              0.032883011666982945f,  0.010597401784997278f}

// Scratch (max live = 8 bands * 320*23^3 = 31.1M floats)
__device__ float g_buf1[31147520];
__device__ float g_buf2[31147520];

// ---------------------------------------------------------------------------
// Forward DWT along a strided axis (level-1 x-pass). Sliding window, 1 row/thread.
// ---------------------------------------------------------------------------
template<int N, int INNER, bool HI>
__global__ void dwt_s(const float* __restrict__ in, float* __restrict__ olo,
                      float* __restrict__ ohi, unsigned total) {
    constexpr int K = (N + 8) / 2 + 1;
    const float LO[8] = FLO;
    const float HIc[8] = FHI;
    unsigned g = blockIdx.x * blockDim.x + threadIdx.x;
    if (g >= total) return;
    unsigned ii = g % INNER;
    unsigned o  = g / INNER;
    const float* bp = in  + (size_t)o * (N * INNER) + ii;
    float*       lp = olo + (size_t)o * (K * INNER) + ii;
    float*       hp = HI ? ohi + (size_t)o * (K * INNER) + ii : nullptr;

    float w[8];
#pragma unroll
    for (int t = 0; t < 8; t++) w[t] = bp[(N - 8 + t) * INNER];

#pragma unroll
    for (int j = 0; j < K; j++) {
        float alo = 0.f, ahi = 0.f;
#pragma unroll
        for (int t = 0; t < 8; t++) {
            alo = fmaf(w[t], LO[7 - t], alo);
            if (HI) ahi = fmaf(w[t], HIc[7 - t], ahi);
        }
        lp[j * INNER] = alo;
        if (HI) hp[j * INNER] = ahi;
        if (j < K - 1) {
            int q0 = (2 * j) % N;
            int q1 = (2 * j + 1) % N;
#pragma unroll
            for (int t = 0; t < 6; t++) w[t] = w[t + 2];
            w[6] = bp[q0 * INNER];
            w[7] = bp[q1 * INNER];
        }
    }
}

// ---------------------------------------------------------------------------
// Level-1 forward, fused y+z, lo-only, paired outputs (R5 version).
// ---------------------------------------------------------------------------
__global__ void f1_yz(const float* __restrict__ in, float* __restrict__ out) {
    __shared__ float s0[64 * 64];
    __shared__ float s1[37 * 65];
    const float LO[8] = FLO;
    unsigned tid = threadIdx.x;
    size_t blk = blockIdx.x;
    const float* gp = in + blk * 4096;
#pragma unroll 4
    for (int t = tid; t < 4096; t += 256) s0[t] = gp[t];
    __syncthreads();
    for (int u = tid; u < 19 * 64; u += 256) {       // y-DWT pairs
        int z = u & 63, jp = u >> 6;
        float w[10];
#pragma unroll
        for (int t = 0; t < 10; t++) {
            int q = (4 * jp - 8 + t) & 63;
            w[t] = s0[q * 64 + z];
        }
        float a0 = 0.f, a1 = 0.f;
#pragma unroll
        for (int s = 0; s < 8; s++) {
            a0 = fmaf(LO[s], w[7 - s], a0);
            a1 = fmaf(LO[s], w[9 - s], a1);
        }
        s1[(2 * jp) * 65 + z] = a0;
        if (2 * jp + 1 < 37) s1[(2 * jp + 1) * 65 + z] = a1;
    }
    __syncthreads();
    float* op = out + blk * 1369;
    for (int u = tid; u < 37 * 19; u += 256) {       // z-DWT pairs
        int ph = u % 19, y = u / 19;
        float w[10];
#pragma unroll
        for (int t = 0; t < 10; t++) {
            int q = (4 * ph - 8 + t) & 63;
            w[t] = s1[y * 65 + q];
        }
        float a0 = 0.f, a1 = 0.f;
#pragma unroll
        for (int s = 0; s < 8; s++) {
            a0 = fmaf(LO[s], w[7 - s], a0);
            a1 = fmaf(LO[s], w[9 - s], a1);
        }
        op[y * 37 + 2 * ph] = a0;
        if (2 * ph + 1 < 37) op[y * 37 + 2 * ph + 1] = a1;
    }
}

// ---------------------------------------------------------------------------
// Level-2 forward, FUSED x+y+z (R13 version).
// ---------------------------------------------------------------------------
__global__ void f2x_yz(const float* __restrict__ in, float* __restrict__ out,
                       long long SBl) {
    __shared__ float s0l[1369], s0h[1369];
    __shared__ float sly[2][23 * 37];
    __shared__ float shy[2][23 * 37];
    const float LO[8] = FLO;
    const float HIc[8] = FHI;
    unsigned tid = threadIdx.x;
    unsigned bc = blockIdx.x / 23;
    int j2 = (int)(blockIdx.x % 23);

    const float* bp = in + (size_t)bc * (37 * 1369);
    int q[8];
#pragma unroll
    for (int t = 0; t < 8; t++) {
        int qq = 2 * j2 - 8 + t;
        if (qq < 0) qq += 37; else if (qq >= 37) qq -= 37;
        q[t] = qq;
    }
    for (int t = tid; t < 1369; t += 256) {
        float al = 0.f, ah = 0.f;
#pragma unroll
        for (int tt = 0; tt < 8; tt++) {
            float v = bp[(size_t)q[tt] * 1369 + t];
            al = fmaf(v, LO[7 - tt], al);
            ah = fmaf(v, HIc[7 - tt], ah);
        }
        s0l[t] = al;
        s0h[t] = ah;
    }
    __syncthreads();

    for (int u = tid; u < 2 * 12 * 37; u += 256) {
        int v  = u / (12 * 37);
        int v2 = u % (12 * 37);
        int z = v2 % 37, jp = v2 / 37;
        const float* s0 = v ? s0h : s0l;
        float w[10];
#pragma unroll
        for (int t = 0; t < 10; t++) {
            int qq = 4 * jp - 8 + t;
            if (qq < 0) qq += 37; else if (qq >= 37) qq -= 37;
            w[t] = s0[qq * 37 + z];
        }
        float l0 = 0.f, h0 = 0.f, l1 = 0.f, h1 = 0.f;
#pragma unroll
        for (int s = 0; s < 8; s++) {
            l0 = fmaf(LO[s],  w[7 - s], l0);
            h0 = fmaf(HIc[s], w[7 - s], h0);
            l1 = fmaf(LO[s],  w[9 - s], l1);
            h1 = fmaf(HIc[s], w[9 - s], h1);
        }
        sly[v][(2 * jp) * 37 + z] = l0;
        shy[v][(2 * jp) * 37 + z] = h0;
        if (2 * jp + 1 < 23) {
            sly[v][(2 * jp + 1) * 37 + z] = l1;
            shy[v][(2 * jp + 1) * 37 + z] = h1;
        }
    }
    __syncthreads();

    size_t obase = ((size_t)bc * 23 + j2) * 529;
    for (int u = tid; u < 2 * 23 * 12; u += 256) {
        int v  = u / (23 * 12);
        int v2 = u % (23 * 12);
        int ph = v2 % 12, y = v2 / 12;
        const float* sl = sly[v];
        const float* sh = shy[v];
        float wl[10], wh[10];
#pragma unroll
        for (int t = 0; t < 10; t++) {
            int qq = 4 * ph - 8 + t;
            if (qq < 0) qq += 37; else if (qq >= 37) qq -= 37;
            wl[t] = sl[y * 37 + qq];
            wh[t] = sh[y * 37 + qq];
        }
        float ll0 = 0.f, lh0 = 0.f, hl0 = 0.f, hh0 = 0.f;
        float ll1 = 0.f, lh1 = 0.f, hl1 = 0.f, hh1 = 0.f;
#pragma unroll
        for (int s = 0; s < 8; s++) {
            ll0 = fmaf(LO[s],  wl[7 - s], ll0);  lh0 = fmaf(HIc[s], wl[7 - s], lh0);
            hl0 = fmaf(LO[s],  wh[7 - s], hl0);  hh0 = fmaf(HIc[s], wh[7 - s], hh0);
            ll1 = fmaf(LO[s],  wl[9 - s], ll1);  lh1 = fmaf(HIc[s], wl[9 - s], lh1);
            hl1 = fmaf(LO[s],  wh[9 - s], hl1);  hh1 = fmaf(HIc[s], wh[9 - s], hh1);
        }
        float* ob = out + (size_t)(4 * v) * SBl + obase + y * 23 + 2 * ph;
        ob[0]           = ll0;
        ob[SBl]         = lh0;
        ob[2 * SBl]     = hl0;
        ob[3 * SBl]     = hh0;
        if (2 * ph + 1 < 23) {
            ob[1]           = ll1;
            ob[SBl + 1]     = lh1;
            ob[2 * SBl + 1] = hl1;
            ob[3 * SBl + 1] = hh1;
        }
    }
}

// ---------------------------------------------------------------------------
// Level-2 inverse, FUSED x+z+y, register-streamed x-IDWT (R12, proven).
// ---------------------------------------------------------------------------
__global__ void i2x_zy(const float* __restrict__ in, float* __restrict__ out,
                       long long SBl) {
    __shared__ float sie[4 * 529];
    __shared__ float sio[4 * 529];
    __shared__ float sle[23 * 37], she[23 * 37];
    __shared__ float slo[23 * 37], sho[23 * 37];
    const float LO[8] = FLO;
    const float HIc[8] = FHI;
    unsigned tid = threadIdx.x;
    unsigned bc = blockIdx.x / 10;
    unsigned xb = blockIdx.x % 10;

    for (int c = 0; c < 2; c++) {
        int xo0 = 4 * (int)xb + 2 * c;
        if (xo0 > 36) break;
        int js = 2 * (int)xb + 1 + c;

        for (int u = tid; u < 4 * 529; u += 256) {
            int m = u / 529, r = u % 529;
            const float* lp = in + (size_t)m * SBl
                              + (size_t)bc * 12167 + (size_t)js * 529 + r;
            const float* hp = lp + 4 * SBl;
            float ae = 0.f, ao = 0.f;
#pragma unroll
            for (int d = 0; d < 4; d++) {
                float vl = lp[d * 529];
                float vh = hp[d * 529];
                ae = fmaf(vl, LO[2 * d + 1], ae);  ae = fmaf(vh, HIc[2 * d + 1], ae);
                ao = fmaf(vl, LO[2 * d],     ao);  ao = fmaf(vh, HIc[2 * d],     ao);
            }
            sie[u] = ae;
            sio[u] = ao;
        }
        __syncthreads();

        for (int u = tid; u < 2 * 23 * 19; u += 256) {
            int p  = u / 437;
            int v2 = u % 437;
            int m  = v2 % 19, y = v2 / 19;
            const float* si = p ? sio : sie;
            float* sl = p ? slo : sle;
            float* sh = p ? sho : she;
            int jz = m + 1;
            float a0 = 0.f, a1 = 0.f, b0 = 0.f, b1 = 0.f;
#pragma unroll
            for (int d = 0; d < 4; d++) {
                int qq = y * 23 + jz + d;
                float v0 = si[qq],           v1 = si[529 + qq];
                float v2f = si[2 * 529 + qq], v3 = si[3 * 529 + qq];
                a0 = fmaf(v0, LO[2 * d + 1], a0);  a0 = fmaf(v1, HIc[2 * d + 1], a0);
                a1 = fmaf(v0, LO[2 * d],     a1);  a1 = fmaf(v1, HIc[2 * d],     a1);
                b0 = fmaf(v2f, LO[2 * d + 1], b0); b0 = fmaf(v3, HIc[2 * d + 1], b0);
                b1 = fmaf(v2f, LO[2 * d],     b1); b1 = fmaf(v3, HIc[2 * d],     b1);
            }
            sl[y * 37 + 2 * m] = a0;  sh[y * 37 + 2 * m] = b0;
            if (2 * m + 1 < 37) {
                sl[y * 37 + 2 * m + 1] = a1;  sh[y * 37 + 2 * m + 1] = b1;
            }
        }
        __syncthreads();

        for (int u = tid; u < 2 * 19 * 37; u += 256) {
            int p  = u / 703;
            int xo = xo0 + p;
            if (xo > 36) continue;
            int v2 = u % 703;
            int z  = v2 % 37, m = v2 / 37;
            const float* sl = p ? slo : sle;
            const float* sh = p ? sho : she;
            int jy = m + 1;
            float a0 = 0.f, a1 = 0.f;
#pragma unroll
            for (int d = 0; d < 4; d++) {
                float vl = sl[(jy + d) * 37 + z];
                float vh = sh[(jy + d) * 37 + z];
                a0 = fmaf(vl, LO[2 * d + 1], a0);  a0 = fmaf(vh, HIc[2 * d + 1], a0);
                a1 = fmaf(vl, LO[2 * d],     a1);  a1 = fmaf(vh, HIc[2 * d],     a1);
            }
            float* op = out + ((size_t)bc * 37 + xo) * 1369;
            op[(2 * m) * 37 + z] = a0;
            if (2 * m + 1 < 37) op[(2 * m + 1) * 37 + z] = a1;
        }
        __syncthreads();
    }
}

// ---------------------------------------------------------------------------
// Level-1 inverse, FUSED x+z+y, lo-only (R9 version, proven).
// ---------------------------------------------------------------------------
__global__ void i1x_yz(const float* __restrict__ in, float* __restrict__ out) {
    __shared__ float ss[5 * 1369];
    __shared__ float s0[1369];
    __shared__ float s1[37 * 65];
    const float LO[8] = FLO;
    unsigned tid = threadIdx.x;
    unsigned bc = blockIdx.x >> 4;
    unsigned xb = blockIdx.x & 15;
    int j0 = 2 * (int)xb + 1;

    const float* gp = in + ((size_t)bc * 37 + j0) * 1369;
#pragma unroll 2
    for (int t = tid; t < 5 * 1369; t += 256) ss[t] = gp[t];
    __syncthreads();

#pragma unroll
    for (int c = 0; c < 4; c++) {
        int xo  = 4 * (int)xb + c;
        int par = c & 1;
        int off = (c >> 1) * 1369;

        for (int t = tid; t < 1369; t += 256) {
            float a = 0.f;
#pragma unroll
            for (int d = 0; d < 4; d++) {
                float fl = par ? LO[2 * d] : LO[2 * d + 1];
                a = fmaf(ss[off + d * 1369 + t], fl, a);
            }
            s0[t] = a;
        }
        __syncthreads();

        for (int u = tid; u < 37 * 32; u += 256) {
            int m = u & 31, y = u >> 5;
            int js = m + 1;
            float a0 = 0.f, a1 = 0.f;
#pragma unroll
            for (int d = 0; d < 4; d++) {
                float v = s0[y * 37 + js + d];
                a0 = fmaf(v, LO[2 * d + 1], a0);
                a1 = fmaf(v, LO[2 * d],     a1);
            }
            s1[y * 65 + 2 * m]     = a0;
            s1[y * 65 + 2 * m + 1] = a1;
        }
        __syncthreads();

        float* op = out + ((size_t)bc * 64 + xo) * 4096;
        for (int u = tid; u < 32 * 64; u += 256) {
            int z = u & 63, m = u >> 6;
            int js = m + 1;
            float a0 = 0.f, a1 = 0.f;
#pragma unroll
            for (int d = 0; d < 4; d++) {
                float v = s1[(js + d) * 65 + z];
                a0 = fmaf(v, LO[2 * d + 1], a0);
                a1 = fmaf(v, LO[2 * d],     a1);
            }
            op[(2 * m) * 64 + z]     = a0;
            op[(2 * m + 1) * 64 + z] = a1;
        }
        __syncthreads();
    }
}

// ---------------------------------------------------------------------------
// Channel mix, ALL 8 bands in one launch (blockIdx.y = band).
// R14 tiling: block (32, 20); each thread owns 2 o-values x 8 batches
// (acc[2][8] = 16 regs vs 40 before) -> ~45 regs -> 2 blocks x 640 thr/SM
// = 62.5% occupancy (was regfile-bound at 37.5%).
// ---------------------------------------------------------------------------
__global__ void chanmix_all(const float* __restrict__ in,
                            float* __restrict__ out, long long SBl,
                            const float* __restrict__ w0, const float* __restrict__ w1,
                            const float* __restrict__ w2, const float* __restrict__ w3,
                            const float* __restrict__ w4, const float* __restrict__ w5,
                            const float* __restrict__ w6, const float* __restrict__ w7) {
    __shared__ float s_in[320][32];
    int k = blockIdx.y;
    const float* w;
    switch (k) {
        case 0: w = w0; break; case 1: w = w1; break;
        case 2: w = w2; break; case 3: w = w3; break;
        case 4: w = w4; break; case 5: w = w5; break;
        case 6: w = w6; break; default: w = w7; break;
    }
    const float* bin  = in  + (long long)k * SBl;
    float*       bout = out + (long long)k * SBl;

    int lane = threadIdx.x;
    int ty   = threadIdx.y;              // 0..19
    int v    = blockIdx.x * 32 + lane;
    bool valid = v < NV;
    int vc = valid ? v : (NV - 1);

    for (int r = ty; r < 320; r += 20)
        s_in[r][lane] = bin[(long long)r * NV + vc];
    __syncthreads();

    float acc[2][8];
#pragma unroll
    for (int a = 0; a < 2; a++)
#pragma unroll
        for (int b = 0; b < 8; b++) acc[a][b] = 0.f;

#pragma unroll 2
    for (int i = 0; i < 40; i += 2) {
        float xv0[8], xv1[8];
#pragma unroll
        for (int b = 0; b < 8; b++) {
            xv0[b] = s_in[b * 40 + i][lane];
            xv1[b] = s_in[b * 40 + i + 1][lane];
        }
        float wv0[2], wv1[2];
#pragma unroll
        for (int oo = 0; oo < 2; oo++) {
            int o = ty + oo * 20;
            wv0[oo] = w[((long long)i * 40 + o) * NV + vc];
            wv1[oo] = w[((long long)(i + 1) * 40 + o) * NV + vc];
        }
#pragma unroll
        for (int oo = 0; oo < 2; oo++)
#pragma unroll
            for (int b = 0; b < 8; b++) {
                acc[oo][b] = fmaf(xv0[b], wv0[oo], acc[oo][b]);
                acc[oo][b] = fmaf(xv1[b], wv1[oo], acc[oo][b]);
            }
    }
    if (!valid) return;
#pragma unroll
    for (int oo = 0; oo < 2; oo++) {
        int o = ty + oo * 20;
#pragma unroll
        for (int b = 0; b < 8; b++)
            bout[((long long)b * 40 + o) * NV + v] = acc[oo][b];
    }
}

// ---------------------------------------------------------------------------
extern "C" void kernel_launch(void* const* d_in, const int* in_sizes, int n_in,
                              void* d_out, int out_size) {
    const float* x = (const float*)d_in[0];
    float* out = (float*)d_out;

    float *b1, *b2;
    cudaGetSymbolAddress((void**)&b1, g_buf1);
    cudaGetSymbolAddress((void**)&b2, g_buf2);

    const long long SBl = 3893440LL;   // 320*23*23*23 (per final band volume)

    auto g = [](unsigned t) { return (t + 255u) / 256u; };

    // --- Level-1 forward: fused yz (lo), then x (lo) ------------------------
    f1_yz<<<320 * 64, 256>>>(x, b1);                        // -> (320,64,37,37)
    { unsigned T = 320u * 1369u;                            // -> (320,37,37,37)
      dwt_s<64, 1369, false><<<g(T), 256>>>(b1, b2, nullptr, T); }

    // --- Level-2 forward: FUSED x (streamed) + yz -> 8 bands -----------------
    f2x_yz<<<320 * 23, 256>>>(b2, b1, SBl);                 // -> 8x(320,23,23,23)

    // --- Channel mix: all 8 bands, re-tiled (32x20) --------------------------
    chanmix_all<<<dim3((NV + 31) / 32, 8), dim3(32, 20)>>>(
        b1, b2, SBl,
        (const float*)d_in[1], (const float*)d_in[2],
        (const float*)d_in[3], (const float*)d_in[4],
        (const float*)d_in[5], (const float*)d_in[6],
        (const float*)d_in[7], (const float*)d_in[8]);

    // --- Level-2 inverse: FUSED x+zy, register-streamed x-IDWT --------------
    i2x_zy<<<320 * 10, 256>>>(b2, b1, SBl);                 // -> (320,37,37,37)

    // --- Level-1 inverse: FUSED x+zy (lo) ------------------------------------
    i1x_yz<<<320 * 16, 256>>>(b1, out);                     // -> (320,64,64,64)
}